// round 8
// baseline (speedup 1.0000x reference)
#include <cuda_runtime.h>

#define NN 10000
#define EE 160000
#define GG 64
#define HH 32
#define WIDTH 64   // ELL width; degree ~ Binomial(160k, 1e-4), P(>=64) ~ 1e-20

// ---- scratch (device globals; referenced ONLY in device code) ----
__device__ float  d_deg[NN];            // 1 + sum of incoming edge weights
__device__ int    d_count[NN];          // per-dst edge count / ELL fill cursor
__device__ float2 d_ell[NN * WIDTH];    // after k_norm: {src as int bits, full norm}; padded slots {0,0}
__device__ float  d_xt[NN * GG];        // x transposed (N, G)
__device__ float  d_zt[NN * GG];        // layer-1 output transposed
__device__ float  d_ot[NN * GG];        // layer-2 output transposed

// ---- K_A: fused init (deg=1, count=0) + transpose x (G,N) -> (N,G) ----
__global__ void k_prep(const float* __restrict__ x) {
    int flat = (blockIdx.y * gridDim.x + blockIdx.x) * 1024 + threadIdx.y * 32 + threadIdx.x;
    if (flat < NN) { d_deg[flat] = 1.0f; d_count[flat] = 0; }

    __shared__ float t[32][33];
    int n0 = blockIdx.x * 32, g0 = blockIdx.y * 32;
    int tx = threadIdx.x, ty = threadIdx.y;
    int n = n0 + tx, g = g0 + ty;
    if (n < NN) t[ty][tx] = x[g * NN + n];
    __syncthreads();
    n = n0 + ty; g = g0 + tx;
    if (n < NN) d_xt[n * GG + g] = t[tx][ty];
}

// ---- K_B: single edge pass: ELL build + degree accumulate (2 edges/thread) ----
__global__ void k_build(const int* __restrict__ ei, const float* __restrict__ w) {
    int i = blockIdx.x * blockDim.x + threadIdx.x;
    if (i < EE / 2) {
        int2   s2 = ((const int2*)ei)[i];            // src pair
        int2   d2 = ((const int2*)ei)[EE / 2 + i];   // dst pair (dst base = ei+EE)
        float2 w2 = ((const float2*)w)[i];

        int p0 = atomicAdd(&d_count[d2.x], 1);
        if (p0 < WIDTH) d_ell[d2.x * WIDTH + p0] = make_float2(__int_as_float(s2.x), w2.x);
        atomicAdd(&d_deg[d2.x], w2.x);

        int p1 = atomicAdd(&d_count[d2.y], 1);
        if (p1 < WIDTH) d_ell[d2.y * WIDTH + p1] = make_float2(__int_as_float(s2.y), w2.y);
        atomicAdd(&d_deg[d2.y], w2.y);
    }
}

// ---- K_C: pre-normalize ELL entries: w -> dinv[src]*w*dinv[dst] ----
__global__ void k_norm() {
    int row = blockIdx.x * 4 + (threadIdx.x >> 6);
    int j   = threadIdx.x & 63;
    if (row < NN && j < d_count[row]) {
        float2 p = d_ell[row * WIDTH + j];
        int s = __float_as_int(p.x);
        d_ell[row * WIDTH + j].y = p.y * rsqrtf(d_deg[s]) * rsqrtf(d_deg[row]);
    }
}

// ---- SpMV: 4 warps per row, 2 rows per 256-thread block ----
// Each sub-warp owns float4 pairs (4 edges) at stride 8 float4s; partial float2
// accumulators reduced through smem; sub 0 warp runs the epilogue. Padded ELL
// slots are {0,0} so reading one float4 past an odd count is harmless.
template <int LAYER>
__global__ void k_spmv(const float* __restrict__ Wa, const float* __restrict__ ba,
                       const float* __restrict__ Wb, const float* __restrict__ b2) {
    __shared__ float2 sacc[2][4][32];
    __shared__ float sW1[HH], sB1[HH], sW2[HH];
    int tid = threadIdx.x;
    if (LAYER == 1 && tid < HH) {
        sW1[tid] = Wa[tid];
        sB1[tid] = ba[tid];
        sW2[tid] = Wb[tid];
    }
    int warp = tid >> 5, lane = tid & 31;
    int rloc = warp >> 2;                  // 0..1: row within block
    int sub  = warp & 3;                   // 0..3: edge-quarter within row
    int row  = blockIdx.x * 2 + rloc;      // grid = NN/2 blocks exactly
    const float2* in2 = (const float2*)(LAYER == 1 ? d_xt : d_zt);
    float2*       ou2 = (float2*)      (LAYER == 1 ? d_zt : d_ot);

    int cnt = min(d_count[row], WIDTH);
    int nf4 = (cnt + 1) >> 1;              // active float4s (2 edges each)
    float2 acc = make_float2(0.f, 0.f);
    const float4* ell4 = (const float4*)&d_ell[row * WIDTH];
    for (int q = sub * 2; q < nf4; q += 8) {
        float4 a = ell4[q];
        float4 b = ell4[q + 1];            // q even => q+1 <= 31, in-bounds, maybe padded zeros
        float2 v0 = in2[__float_as_int(a.x) * 32 + lane];
        float2 v1 = in2[__float_as_int(a.z) * 32 + lane];
        float2 v2 = in2[__float_as_int(b.x) * 32 + lane];
        float2 v3 = in2[__float_as_int(b.z) * 32 + lane];
        acc.x = fmaf(a.y, v0.x, acc.x);  acc.y = fmaf(a.y, v0.y, acc.y);
        acc.x = fmaf(a.w, v1.x, acc.x);  acc.y = fmaf(a.w, v1.y, acc.y);
        acc.x = fmaf(b.y, v2.x, acc.x);  acc.y = fmaf(b.y, v2.y, acc.y);
        acc.x = fmaf(b.w, v3.x, acc.x);  acc.y = fmaf(b.w, v3.y, acc.y);
    }
    sacc[rloc][sub][lane] = acc;
    __syncthreads();

    if (sub == 0) {
        float2 a0 = sacc[rloc][0][lane];
        float2 a1 = sacc[rloc][1][lane];
        float2 a2 = sacc[rloc][2][lane];
        float2 a3 = sacc[rloc][3][lane];
        float sn = 1.0f / d_deg[row];      // self-loop norm = dinv^2
        float2 xs = in2[row * 32 + lane];
        float yx = a0.x + a1.x + a2.x + a3.x + sn * xs.x;
        float yy = a0.y + a1.y + a2.y + a3.y + sn * xs.y;

        float2 res;
        if (LAYER == 1) {
            float z0 = 0.f, z1 = 0.f;
            #pragma unroll
            for (int j = 0; j < HH; j++) {
                z0 += fmaxf(fmaf(yx, sW1[j], sB1[j]), 0.f) * sW2[j];
                z1 += fmaxf(fmaf(yy, sW1[j], sB1[j]), 0.f) * sW2[j];
            }
            res = make_float2(z0, z1);
        } else {
            float bb = __ldg(b2);
            res = make_float2(yx + bb, yy + bb);
        }
        ou2[row * 32 + lane] = res;
    }
}

// ---- K_F: transpose out (N,G)->(G,N) fused with mask merge (mask is int32) ----
__global__ void k_out(const float* __restrict__ x, const int* __restrict__ mask,
                      float* __restrict__ out) {
    __shared__ float t[32][33];
    int n0 = blockIdx.x * 32, g0 = blockIdx.y * 32;
    int tx = threadIdx.x, ty = threadIdx.y;
    int n = n0 + ty, g = g0 + tx;
    if (n < NN) t[ty][tx] = d_ot[n * GG + g];
    __syncthreads();
    n = n0 + tx; g = g0 + ty;
    if (n < NN) {
        int idx = g * NN + n;
        out[idx] = mask[idx] ? x[idx] : t[tx][ty];
    }
}

extern "C" void kernel_launch(void* const* d_in, const int* in_sizes, int n_in,
                              void* d_out, int out_size) {
    const float* x    = (const float*)d_in[0];
    const int*   mask = (const int*)d_in[1];      // jax bool -> int32 on the wire
    const int*   ei   = (const int*)d_in[2];
    const float* w    = (const float*)d_in[3];
    const float* W1   = (const float*)d_in[4];
    const float* b1   = (const float*)d_in[5];
    const float* W2   = (const float*)d_in[6];
    const float* b2   = (const float*)d_in[7];
    float*       out  = (float*)d_out;

    dim3 tb(32, 32);
    dim3 tg((NN + 31) / 32, GG / 32);
    k_prep<<<tg, tb>>>(x);
    k_build<<<(EE / 2 + 255) / 256, 256>>>(ei, w);
    k_norm<<<(NN + 3) / 4, 256>>>();
    k_spmv<1><<<NN / 2, 256>>>(W1, b1, W2, b2);   // 2 rows/block, 4 warps/row
    k_spmv<2><<<NN / 2, 256>>>(W1, b1, W2, b2);
    k_out<<<tg, tb>>>(x, mask, out);
}

// round 9
// speedup vs baseline: 1.1643x; 1.1643x over previous
#include <cuda_runtime.h>

#define NN 10000
#define EE 160000
#define GG 64
#define HH 32
#define WIDTH 64   // ELL width; degree ~ Binomial(160k, 1e-4), P(>=64) ~ 1e-20

// ---- scratch (device globals; referenced ONLY in device code) ----
__device__ float  d_deg[NN];            // 1 + sum of incoming edge weights
__device__ int    d_count[NN];          // per-dst edge count / ELL fill cursor
__device__ float2 d_ell[NN * WIDTH];    // after k_norm: {src as int bits, full norm}; padded slots {0,0}
__device__ float  d_xt[NN * GG];        // x transposed (N, G)
__device__ float  d_zt[NN * GG];        // layer-1 output transposed
__device__ float  d_ot[NN * GG];        // layer-2 output transposed

// ---- K_A: fused init (deg=1, count=0) + transpose x (G,N) -> (N,G) ----
__global__ void k_prep(const float* __restrict__ x) {
    int flat = (blockIdx.y * gridDim.x + blockIdx.x) * 1024 + threadIdx.y * 32 + threadIdx.x;
    if (flat < NN) { d_deg[flat] = 1.0f; d_count[flat] = 0; }

    __shared__ float t[32][33];
    int n0 = blockIdx.x * 32, g0 = blockIdx.y * 32;
    int tx = threadIdx.x, ty = threadIdx.y;
    int n = n0 + tx, g = g0 + ty;
    if (n < NN) t[ty][tx] = x[g * NN + n];
    __syncthreads();
    n = n0 + ty; g = g0 + tx;
    if (n < NN) d_xt[n * GG + g] = t[tx][ty];
}

// ---- K_B: single edge pass: ELL build + degree accumulate (2 edges/thread) ----
__global__ void k_build(const int* __restrict__ ei, const float* __restrict__ w) {
    int i = blockIdx.x * blockDim.x + threadIdx.x;
    if (i < EE / 2) {
        int2   s2 = ((const int2*)ei)[i];            // src pair
        int2   d2 = ((const int2*)ei)[EE / 2 + i];   // dst pair (dst base = ei+EE)
        float2 w2 = ((const float2*)w)[i];

        int p0 = atomicAdd(&d_count[d2.x], 1);
        if (p0 < WIDTH) d_ell[d2.x * WIDTH + p0] = make_float2(__int_as_float(s2.x), w2.x);
        atomicAdd(&d_deg[d2.x], w2.x);

        int p1 = atomicAdd(&d_count[d2.y], 1);
        if (p1 < WIDTH) d_ell[d2.y * WIDTH + p1] = make_float2(__int_as_float(s2.y), w2.y);
        atomicAdd(&d_deg[d2.y], w2.y);
    }
}

// ---- K_C: pre-normalize ELL entries: w -> dinv[src]*w*dinv[dst] ----
__global__ void k_norm() {
    int row = blockIdx.x * 4 + (threadIdx.x >> 6);
    int j   = threadIdx.x & 63;
    if (row < NN && j < d_count[row]) {
        float2 p = d_ell[row * WIDTH + j];
        int s = __float_as_int(p.x);
        d_ell[row * WIDTH + j].y = p.y * rsqrtf(d_deg[s]) * rsqrtf(d_deg[row]);
    }
}

// ---- SpMV: warp-per-row, 2 replicas/lane, register-staged ELL + shfl broadcast ----
// Lane l holds ELL slots l and l+32 in registers (2 coalesced LDG.64 = ONE latency
// window for all row metadata). Per 8-edge chunk: shfl-broadcast the 8 {src,norm}
// pairs from registers (no memory), then issue 8 INDEPENDENT gathers whose
// addresses never wait on an in-flight LDG. Padded slots are {0,0} -> no-ops.
template <int LAYER>
__global__ void k_spmv(const float* __restrict__ Wa, const float* __restrict__ ba,
                       const float* __restrict__ Wb, const float* __restrict__ b2) {
    __shared__ float sW1[HH], sB1[HH], sW2[HH];
    if (LAYER == 1) {
        if (threadIdx.x < HH) {
            sW1[threadIdx.x] = Wa[threadIdx.x];
            sB1[threadIdx.x] = ba[threadIdx.x];
            sW2[threadIdx.x] = Wb[threadIdx.x];
        }
        __syncthreads();
    }

    int row  = (blockIdx.x * blockDim.x + threadIdx.x) >> 5;   // grid = exactly NN warps
    int lane = threadIdx.x & 31;
    const float2* in2 = (const float2*)(LAYER == 1 ? d_xt : d_zt);
    float2*       ou2 = (float2*)      (LAYER == 1 ? d_zt : d_ot);

    const float2* ell2 = d_ell + row * WIDTH;
    float2 elo = ell2[lane];          // slots 0..31   (coalesced 256B)
    float2 ehi = ell2[32 + lane];     // slots 32..63  (coalesced 256B, independent)

    float sn = 1.0f / d_deg[row];     // self-loop norm = dinv^2
    float2 xs = in2[row * 32 + lane];
    float2 acc = make_float2(sn * xs.x, sn * xs.y);

    int cnt = min(d_count[row], WIDTH);
    for (int base = 0; base < cnt; base += 8) {
        float ex = (base & 32) ? ehi.x : elo.x;   // uniform half-select, branchless
        float ey = (base & 32) ? ehi.y : elo.y;
        int b = base & 31;                         // b in {0,8,16,24}; b+7 <= 31
        int   s0 = __float_as_int(__shfl_sync(0xffffffffu, ex, b + 0));
        int   s1 = __float_as_int(__shfl_sync(0xffffffffu, ex, b + 1));
        int   s2 = __float_as_int(__shfl_sync(0xffffffffu, ex, b + 2));
        int   s3 = __float_as_int(__shfl_sync(0xffffffffu, ex, b + 3));
        int   s4 = __float_as_int(__shfl_sync(0xffffffffu, ex, b + 4));
        int   s5 = __float_as_int(__shfl_sync(0xffffffffu, ex, b + 5));
        int   s6 = __float_as_int(__shfl_sync(0xffffffffu, ex, b + 6));
        int   s7 = __float_as_int(__shfl_sync(0xffffffffu, ex, b + 7));
        float n0 = __shfl_sync(0xffffffffu, ey, b + 0);
        float n1 = __shfl_sync(0xffffffffu, ey, b + 1);
        float n2 = __shfl_sync(0xffffffffu, ey, b + 2);
        float n3 = __shfl_sync(0xffffffffu, ey, b + 3);
        float n4 = __shfl_sync(0xffffffffu, ey, b + 4);
        float n5 = __shfl_sync(0xffffffffu, ey, b + 5);
        float n6 = __shfl_sync(0xffffffffu, ey, b + 6);
        float n7 = __shfl_sync(0xffffffffu, ey, b + 7);
        // 8 independent gathers; addresses depend only on registers
        float2 v0 = in2[s0 * 32 + lane];
        float2 v1 = in2[s1 * 32 + lane];
        float2 v2 = in2[s2 * 32 + lane];
        float2 v3 = in2[s3 * 32 + lane];
        float2 v4 = in2[s4 * 32 + lane];
        float2 v5 = in2[s5 * 32 + lane];
        float2 v6 = in2[s6 * 32 + lane];
        float2 v7 = in2[s7 * 32 + lane];
        acc.x = fmaf(n0, v0.x, acc.x);  acc.y = fmaf(n0, v0.y, acc.y);
        acc.x = fmaf(n1, v1.x, acc.x);  acc.y = fmaf(n1, v1.y, acc.y);
        acc.x = fmaf(n2, v2.x, acc.x);  acc.y = fmaf(n2, v2.y, acc.y);
        acc.x = fmaf(n3, v3.x, acc.x);  acc.y = fmaf(n3, v3.y, acc.y);
        acc.x = fmaf(n4, v4.x, acc.x);  acc.y = fmaf(n4, v4.y, acc.y);
        acc.x = fmaf(n5, v5.x, acc.x);  acc.y = fmaf(n5, v5.y, acc.y);
        acc.x = fmaf(n6, v6.x, acc.x);  acc.y = fmaf(n6, v6.y, acc.y);
        acc.x = fmaf(n7, v7.x, acc.x);  acc.y = fmaf(n7, v7.y, acc.y);
    }

    float2 res;
    if (LAYER == 1) {
        float z0 = 0.f, z1 = 0.f;
        #pragma unroll
        for (int j = 0; j < HH; j++) {
            z0 += fmaxf(fmaf(acc.x, sW1[j], sB1[j]), 0.f) * sW2[j];
            z1 += fmaxf(fmaf(acc.y, sW1[j], sB1[j]), 0.f) * sW2[j];
        }
        res = make_float2(z0, z1);
    } else {
        float bb = __ldg(b2);
        res = make_float2(acc.x + bb, acc.y + bb);
    }
    ou2[row * 32 + lane] = res;
}

// ---- K_F: transpose out (N,G)->(G,N) fused with mask merge (mask is int32) ----
__global__ void k_out(const float* __restrict__ x, const int* __restrict__ mask,
                      float* __restrict__ out) {
    __shared__ float t[32][33];
    int n0 = blockIdx.x * 32, g0 = blockIdx.y * 32;
    int tx = threadIdx.x, ty = threadIdx.y;
    int n = n0 + ty, g = g0 + tx;
    if (n < NN) t[ty][tx] = d_ot[n * GG + g];
    __syncthreads();
    n = n0 + tx; g = g0 + ty;
    if (n < NN) {
        int idx = g * NN + n;
        out[idx] = mask[idx] ? x[idx] : t[tx][ty];
    }
}

extern "C" void kernel_launch(void* const* d_in, const int* in_sizes, int n_in,
                              void* d_out, int out_size) {
    const float* x    = (const float*)d_in[0];
    const int*   mask = (const int*)d_in[1];      // jax bool -> int32 on the wire
    const int*   ei   = (const int*)d_in[2];
    const float* w    = (const float*)d_in[3];
    const float* W1   = (const float*)d_in[4];
    const float* b1   = (const float*)d_in[5];
    const float* W2   = (const float*)d_in[6];
    const float* b2   = (const float*)d_in[7];
    float*       out  = (float*)d_out;

    dim3 tb(32, 32);
    dim3 tg((NN + 31) / 32, GG / 32);
    k_prep<<<tg, tb>>>(x);
    k_build<<<(EE / 2 + 255) / 256, 256>>>(ei, w);
    k_norm<<<(NN + 3) / 4, 256>>>();
    k_spmv<1><<<NN / 8, 256>>>(W1, b1, W2, b2);   // warp-per-row, 8 warps/block
    k_spmv<2><<<NN / 8, 256>>>(W1, b1, W2, b2);
    k_out<<<tg, tb>>>(x, mask, out);
}